// round 3
// baseline (speedup 1.0000x reference)
#include <cuda_runtime.h>
#include <cuda_bf16.h>
#include <cstdint>

// KANLayer: out[b] = sum_{d,h} tanh(x[b,d]*w1[d,h] + b1[d,h]) * w2[d,h] + sum_d b2[d]
// B=65536, D=256, H=16.
//
// Math transform (MUFU-minimal):
//   tanh(y) = 1 - 2/(1 + exp(2y)) = 1 - 2*rcp(1 + ex2(2*log2e * y))
//   w2*tanh(y) = w2 + (-2*w2)*rcp(1 + ex2(w1s*x + b1s))
// with w1s = 2*log2e*w1, b1s = 2*log2e*b1. The "+w2" terms and b2 fold into one
// scalar constant C. Per (b,d,h) term: FFMA, EX2, FADD, RCP, FFMA.

#define D_DIM 256
#define H_DIM 16
#define DH    (D_DIM * H_DIM)   // 4096
#define B_DIM 65536

// Scratch (allocation-free rule: __device__ globals)
__device__ float g_w1s[DH];
__device__ float g_b1s[DH];
__device__ float g_w2m2[DH];   // -2*w2
__device__ float g_C;          // sum(w2) + sum(b2)

__device__ __forceinline__ float fex2(float v) {
    float r; asm("ex2.approx.f32 %0, %1;" : "=f"(r) : "f"(v)); return r;
}
__device__ __forceinline__ float frcp(float v) {
    float r; asm("rcp.approx.f32 %0, %1;" : "=f"(r) : "f"(v)); return r;
}

// ---------------------------------------------------------------------------
// Prep kernel: scale params, fold constant. One block, deterministic reduce.
// ---------------------------------------------------------------------------
__global__ void kan_prep(const float* __restrict__ w1,
                         const float* __restrict__ b1,
                         const float* __restrict__ w2,
                         const float* __restrict__ b2) {
    const int t = threadIdx.x;                 // 256 threads
    const float k = 2.0f * 1.4426950408889634f; // 2*log2(e)

    float s = 0.0f;
    for (int i = t; i < DH; i += 256) {
        float w2v = w2[i];
        g_w1s[i]  = w1[i] * k;
        g_b1s[i]  = b1[i] * k;
        g_w2m2[i] = -2.0f * w2v;
        s += w2v;
    }
    s += b2[t];   // D=256 == blockDim

    __shared__ float red[256];
    red[t] = s;
    __syncthreads();
    #pragma unroll
    for (int off = 128; off > 0; off >>= 1) {
        if (t < off) red[t] += red[t + off];
        __syncthreads();
    }
    if (t == 0) g_C = red[0];
}

// ---------------------------------------------------------------------------
// Main kernel: 1 thread = 1 output row. Params staged in smem; every warp
// walks the same d sequence so all param LDS are broadcasts (conflict-free).
// ---------------------------------------------------------------------------
__global__ __launch_bounds__(128) void kan_main(const float* __restrict__ x,
                                                float* __restrict__ out) {
    __shared__ float s_w1[DH];
    __shared__ float s_b1[DH];
    __shared__ float s_w2[DH];

    // Cooperative param load (vectorized)
    {
        const float4* gw1 = reinterpret_cast<const float4*>(g_w1s);
        const float4* gb1 = reinterpret_cast<const float4*>(g_b1s);
        const float4* gw2 = reinterpret_cast<const float4*>(g_w2m2);
        float4* sw1 = reinterpret_cast<float4*>(s_w1);
        float4* sb1 = reinterpret_cast<float4*>(s_b1);
        float4* sw2 = reinterpret_cast<float4*>(s_w2);
        for (int i = threadIdx.x; i < DH / 4; i += blockDim.x) {
            sw1[i] = gw1[i];
            sb1[i] = gb1[i];
            sw2[i] = gw2[i];
        }
    }
    __syncthreads();

    const int b = blockIdx.x * blockDim.x + threadIdx.x;

    const float4* xr = reinterpret_cast<const float4*>(x) + (size_t)b * (D_DIM / 4);

    float acc = 0.0f;

    #pragma unroll 4
    for (int d4 = 0; d4 < D_DIM / 4; ++d4) {
        float4 xv = xr[d4];
        #pragma unroll
        for (int j = 0; j < 4; ++j) {
            const float xd = (j == 0) ? xv.x : (j == 1) ? xv.y : (j == 2) ? xv.z : xv.w;
            const int d = d4 * 4 + j;
            const float4* w1p = reinterpret_cast<const float4*>(&s_w1[d * H_DIM]);
            const float4* b1p = reinterpret_cast<const float4*>(&s_b1[d * H_DIM]);
            const float4* w2p = reinterpret_cast<const float4*>(&s_w2[d * H_DIM]);
            #pragma unroll
            for (int q = 0; q < H_DIM / 4; ++q) {
                float4 wa = w1p[q];
                float4 ba = b1p[q];
                float4 ca = w2p[q];

                float t0 = fmaf(xd, wa.x, ba.x);
                float t1 = fmaf(xd, wa.y, ba.y);
                float t2 = fmaf(xd, wa.z, ba.z);
                float t3 = fmaf(xd, wa.w, ba.w);

                float e0 = fex2(t0);
                float e1 = fex2(t1);
                float e2 = fex2(t2);
                float e3 = fex2(t3);

                float r0 = frcp(1.0f + e0);
                float r1 = frcp(1.0f + e1);
                float r2 = frcp(1.0f + e2);
                float r3 = frcp(1.0f + e3);

                acc = fmaf(ca.x, r0, acc);
                acc = fmaf(ca.y, r1, acc);
                acc = fmaf(ca.z, r2, acc);
                acc = fmaf(ca.w, r3, acc);
            }
        }
    }

    out[b] = acc + g_C;
}

// ---------------------------------------------------------------------------
// Launch. Inputs (metadata order): x[B*D], w1[D*H], b1[D*H], w2[D*H], b2[D].
// Output: float[B] (shape [B,1]).
// ---------------------------------------------------------------------------
extern "C" void kernel_launch(void* const* d_in, const int* in_sizes, int n_in,
                              void* d_out, int out_size) {
    const float* x  = (const float*)d_in[0];
    const float* w1 = (const float*)d_in[1];
    const float* b1 = (const float*)d_in[2];
    const float* w2 = (const float*)d_in[3];
    const float* b2 = (const float*)d_in[4];
    float* out = (float*)d_out;

    kan_prep<<<1, 256>>>(w1, b1, w2, b2);
    kan_main<<<B_DIM / 128, 128>>>(x, out);
}

// round 4
// speedup vs baseline: 2.3088x; 2.3088x over previous
#include <cuda_runtime.h>
#include <cuda_bf16.h>
#include <cstdint>

// KANLayer: out[b] = sum_{d,h} tanh(x[b,d]*w1[d,h] + b1[d,h]) * w2[d,h] + sum_d b2[d]
// B=65536, D=256, H=16.
//
// Per-term pipeline (MUFU-minimal, using sm_75+ hardware tanh):
//   FFMA (x*w1+b1)  ->  MUFU.TANH  ->  FFMA (acc += w2*t)
// MUFU: 1 op/term (8 SMSP-cyc/warp-term) binds; FMA: 2 ops (4 cyc) hidden.
// Sum(b2) is reduced in-block (deterministic fixed-order) -- no prep kernel.

#define D_DIM 256
#define H_DIM 16
#define DH    (D_DIM * H_DIM)   // 4096
#define B_DIM 65536
#define TPB   256

__device__ __forceinline__ float ftanh(float v) {
    float r; asm("tanh.approx.f32 %0, %1;" : "=f"(r) : "f"(v)); return r;
}

__global__ __launch_bounds__(TPB, 4) void kan_main(const float* __restrict__ x,
                                                   const float* __restrict__ w1,
                                                   const float* __restrict__ b1,
                                                   const float* __restrict__ w2,
                                                   const float* __restrict__ b2,
                                                   float* __restrict__ out) {
    // Exactly 48KB static smem (the static cap) -- 3 x 4096 floats.
    __shared__ float s_w1[DH];
    __shared__ float s_b1[DH];
    __shared__ float s_w2[DH];

    const int t    = threadIdx.x;
    const int lane = t & 31;
    const int wid  = t >> 5;

    // ---- Sum(b2) via shuffle reduce, using s_w1[0..7] as transient scratch.
    // All threads end with the identical fixed-order value -> deterministic.
    float myb2 = b2[t];  // TPB == D_DIM == 256
    #pragma unroll
    for (int off = 16; off > 0; off >>= 1)
        myb2 += __shfl_xor_sync(0xFFFFFFFFu, myb2, off);
    if (lane == 0) s_w1[wid] = myb2;   // 8 warp partials
    __syncthreads();
    float C = 0.0f;
    #pragma unroll
    for (int i = 0; i < 8; ++i) C += s_w1[i];
    __syncthreads();

    // ---- Stage parameters into smem (vectorized; overwrites scratch).
    {
        const float4* gw1 = reinterpret_cast<const float4*>(w1);
        const float4* gb1 = reinterpret_cast<const float4*>(b1);
        const float4* gw2 = reinterpret_cast<const float4*>(w2);
        float4* sw1 = reinterpret_cast<float4*>(s_w1);
        float4* sb1 = reinterpret_cast<float4*>(s_b1);
        float4* sw2 = reinterpret_cast<float4*>(s_w2);
        #pragma unroll
        for (int i = t; i < DH / 4; i += TPB) {
            sw1[i] = gw1[i];
            sb1[i] = gb1[i];
            sw2[i] = gw2[i];
        }
    }
    __syncthreads();

    // ---- One thread per output row. All lanes of a warp walk the same d
    // sequence, so every param LDS is a broadcast (conflict-free).
    const int b = blockIdx.x * TPB + t;
    const float4* xr = reinterpret_cast<const float4*>(x) + (size_t)b * (D_DIM / 4);

    float acc = 0.0f;

    #pragma unroll 2
    for (int d4 = 0; d4 < D_DIM / 4; ++d4) {
        float4 xv = xr[d4];
        #pragma unroll
        for (int j = 0; j < 4; ++j) {
            const float xd = (j == 0) ? xv.x : (j == 1) ? xv.y : (j == 2) ? xv.z : xv.w;
            const int d = d4 * 4 + j;
            const float4* w1p = reinterpret_cast<const float4*>(&s_w1[d * H_DIM]);
            const float4* b1p = reinterpret_cast<const float4*>(&s_b1[d * H_DIM]);
            const float4* w2p = reinterpret_cast<const float4*>(&s_w2[d * H_DIM]);
            #pragma unroll
            for (int q = 0; q < H_DIM / 4; ++q) {
                float4 wa = w1p[q];
                float4 ba = b1p[q];
                float4 ca = w2p[q];

                float t0 = ftanh(fmaf(xd, wa.x, ba.x));
                float t1 = ftanh(fmaf(xd, wa.y, ba.y));
                float t2 = ftanh(fmaf(xd, wa.z, ba.z));
                float t3 = ftanh(fmaf(xd, wa.w, ba.w));

                acc = fmaf(ca.x, t0, acc);
                acc = fmaf(ca.y, t1, acc);
                acc = fmaf(ca.z, t2, acc);
                acc = fmaf(ca.w, t3, acc);
            }
        }
    }

    out[b] = acc + C;
}

extern "C" void kernel_launch(void* const* d_in, const int* in_sizes, int n_in,
                              void* d_out, int out_size) {
    const float* x  = (const float*)d_in[0];
    const float* w1 = (const float*)d_in[1];
    const float* b1 = (const float*)d_in[2];
    const float* w2 = (const float*)d_in[3];
    const float* b2 = (const float*)d_in[4];
    float* out = (float*)d_out;

    kan_main<<<B_DIM / TPB, TPB>>>(x, w1, b1, w2, b2, out);
}